// round 6
// baseline (speedup 1.0000x reference)
#include <cuda_runtime.h>
#include <cuda_bf16.h>
#include <cstdint>
#include <cstddef>

// Problem constants
#define BATCH 4
#define NSEQ 2048
#define DIM 512
#define NHEAD 8
#define DHEAD 128
#define INNER 1024
#define MROWS (BATCH*NSEQ)  // 8192

#define WIN 16              // sigma<=2.5: tap at d=17 ~ 9e-11 -> negligible
#define TN 64

// ---------------- scratch (allocation-free rule) ----------------
__device__ __align__(16) float          g_y[MROWS * INNER];
__device__ __align__(16) __nv_bfloat16  g_xhi[MROWS * DIM];
__device__ __align__(16) __nv_bfloat16  g_xlo[MROWS * DIM];
__device__ __align__(16) __nv_bfloat16  g_shi[MROWS * INNER];
__device__ __align__(16) __nv_bfloat16  g_slo[MROWS * INNER];
__device__ __align__(16) __nv_bfloat16  g_wgT_hi[INNER * DIM];   // Wg^T  [1024,512]
__device__ __align__(16) __nv_bfloat16  g_wgT_lo[INNER * DIM];
__device__ __align__(16) __nv_bfloat16  g_woT_hi[DIM * INNER];   // Wout^T [512,1024]
__device__ __align__(16) __nv_bfloat16  g_woT_lo[DIM * INNER];

// ---------------- helpers ----------------
typedef unsigned long long ull;
__device__ __forceinline__ ull pack_dup(float a) {
    ull r; asm("mov.b64 %0, {%1, %1};" : "=l"(r) : "f"(a)); return r;
}
__device__ __forceinline__ void ffma2(ull& d, ull a, ull b) {
    asm("fma.rn.f32x2 %0, %1, %2, %0;" : "+l"(d) : "l"(a), "l"(b));
}
__device__ __forceinline__ void unpack2(ull v, float& lo, float& hi) {
    asm("mov.b64 {%0, %1}, %2;" : "=f"(lo), "=f"(hi) : "l"(v));
}
__device__ __forceinline__ uint32_t smem_to_u32(const void* p) {
    uint32_t a;
    asm("{ .reg .u64 t; cvta.to.shared.u64 t, %1; cvt.u32.u64 %0, t; }" : "=r"(a) : "l"(p));
    return a;
}
__device__ __forceinline__ void cp16(uint32_t dst, const void* src) {
    asm volatile("cp.async.cg.shared.global [%0], [%1], 16;" :: "r"(dst), "l"(src) : "memory");
}
#define CP_COMMIT() asm volatile("cp.async.commit_group;" ::: "memory")
#define CP_WAIT1()  asm volatile("cp.async.wait_group 1;" ::: "memory")

__device__ __forceinline__ void ldsm_x4(uint32_t addr, uint32_t& r0, uint32_t& r1,
                                        uint32_t& r2, uint32_t& r3) {
    asm volatile("ldmatrix.sync.aligned.m8n8.x4.shared.b16 {%0,%1,%2,%3}, [%4];"
                 : "=r"(r0), "=r"(r1), "=r"(r2), "=r"(r3) : "r"(addr));
}
__device__ __forceinline__ void mma16816(float* d, const uint32_t* a,
                                         uint32_t b0, uint32_t b1) {
    asm volatile("mma.sync.aligned.m16n8k16.row.col.f32.bf16.bf16.f32 "
                 "{%0,%1,%2,%3}, {%4,%5,%6,%7}, {%8,%9}, {%0,%1,%2,%3};"
                 : "+f"(d[0]), "+f"(d[1]), "+f"(d[2]), "+f"(d[3])
                 : "r"(a[0]), "r"(a[1]), "r"(a[2]), "r"(a[3]), "r"(b0), "r"(b1));
}

// ---------------------------------------------------------------------------
// HMMA GEMM: C[M,N](f32) = (Ahi+Alo)[M,K] @ (Bhi+Blo)^T,  B* stored [N,K].
// CTA tile 128x64, K-chunk 32, 8 warps, warp tile 32x32.
// Products hi*hi + hi*lo + lo*hi in f32 registers.
// 3-stage cp.async pipeline; MMA schedule keyed product-type-outermost so
// same-accumulator reuse is separated by 8 independent HMMAs (RAW hiding).
// ---------------------------------------------------------------------------
#define CTM 128
#define CTN 64
#define TK  32
#define ROWB 80
#define STG_A (CTM * ROWB)                   // 10240
#define STG_B (CTN * ROWB)                   // 5120
#define STAGE_BYTES (2 * STG_A + 2 * STG_B)  // 30720
#define NSTAGE 3
#define SMEM_GEMM (NSTAGE * STAGE_BYTES)     // 92160

__global__ __launch_bounds__(256, 2)
void gemm_mma(const __nv_bfloat16* __restrict__ Ahi, const __nv_bfloat16* __restrict__ Alo,
              const __nv_bfloat16* __restrict__ Bhi, const __nv_bfloat16* __restrict__ Blo,
              float* __restrict__ C, int M, int N, int K) {
    extern __shared__ char smem[];
    const uint32_t sb = smem_to_u32(smem);
    const int tid = threadIdx.x;
    const int wid = tid >> 5;
    const int lane = tid & 31;
    const int row0 = blockIdx.y << 7;
    const int col0 = blockIdx.x << 6;

    const int wm = wid & 3;
    const int wn = wid >> 2;
    const int m0 = wm << 5;
    const int n0 = wn << 5;

    const int arow = tid >> 2;
    const int ac   = (tid & 3) << 3;
    const int acB  = (tid & 3) << 4;

    auto load_stage = [&](int buf, int kc) {
        const uint32_t st = sb + buf * STAGE_BYTES;
#pragma unroll
        for (int r = 0; r < 2; r++) {
            const int row = arow + 64 * r;
            const uint32_t d = st + row * ROWB + acB;
            const size_t e = (size_t)(row0 + row) * K + kc + ac;
            cp16(d, Ahi + e);
            cp16(d + STG_A, Alo + e);
        }
        {
            const uint32_t d = st + 2 * STG_A + arow * ROWB + acB;
            const size_t e = (size_t)(col0 + arow) * K + kc + ac;
            cp16(d, Bhi + e);
            cp16(d + STG_B, Blo + e);
        }
    };

    float d[2][4][4];
#pragma unroll
    for (int i = 0; i < 2; i++)
#pragma unroll
        for (int j = 0; j < 4; j++)
#pragma unroll
            for (int q = 0; q < 4; q++) d[i][j][q] = 0.f;

    const int KT = K / TK;
    load_stage(0, 0);  CP_COMMIT();
    load_stage(1, TK); CP_COMMIT();

    const uint32_t a_lane_off = (uint32_t)((lane & 15) * ROWB + ((lane >> 4) << 4));
    const uint32_t b_lane_off = (uint32_t)((((lane >> 4) << 3) + (lane & 7)) * ROWB
                                           + (((lane >> 3) & 1) << 4));

    int cur = 0;
    int nxt2 = 2;
    for (int kt = 0; kt < KT; kt++) {
        CP_WAIT1();
        __syncthreads();

        if (kt + 2 < KT) load_stage(nxt2, (kt + 2) * TK);
        CP_COMMIT();

        const uint32_t st = sb + cur * STAGE_BYTES;
#pragma unroll
        for (int s = 0; s < 2; s++) {
            uint32_t ah[2][4], al[2][4], bh[2][4], bl[2][4];
#pragma unroll
            for (int i = 0; i < 2; i++) {
                const uint32_t aa = st + (uint32_t)((m0 + i * 16) * ROWB + s * 32) + a_lane_off;
                ldsm_x4(aa, ah[i][0], ah[i][1], ah[i][2], ah[i][3]);
                ldsm_x4(aa + STG_A, al[i][0], al[i][1], al[i][2], al[i][3]);
            }
#pragma unroll
            for (int g = 0; g < 2; g++) {
                const uint32_t ba = st + 2 * STG_A
                                  + (uint32_t)((n0 + g * 16) * ROWB + s * 32) + b_lane_off;
                ldsm_x4(ba, bh[g][0], bh[g][1], bh[g][2], bh[g][3]);
                ldsm_x4(ba + STG_B, bl[g][0], bl[g][1], bl[g][2], bl[g][3]);
            }
            // product-type OUTERMOST: 8 independent accumulators between any
            // two HMMAs that share an accumulator (breaks the RAW chain).
#pragma unroll
            for (int i = 0; i < 2; i++)
#pragma unroll
                for (int g = 0; g < 2; g++)
#pragma unroll
                    for (int jj = 0; jj < 2; jj++)
                        mma16816(d[i][g * 2 + jj], ah[i], bh[g][jj * 2], bh[g][jj * 2 + 1]);
#pragma unroll
            for (int i = 0; i < 2; i++)
#pragma unroll
                for (int g = 0; g < 2; g++)
#pragma unroll
                    for (int jj = 0; jj < 2; jj++)
                        mma16816(d[i][g * 2 + jj], ah[i], bl[g][jj * 2], bl[g][jj * 2 + 1]);
#pragma unroll
            for (int i = 0; i < 2; i++)
#pragma unroll
                for (int g = 0; g < 2; g++)
#pragma unroll
                    for (int jj = 0; jj < 2; jj++)
                        mma16816(d[i][g * 2 + jj], al[i], bh[g][jj * 2], bh[g][jj * 2 + 1]);
        }
        cur  = (cur == 2)  ? 0 : cur + 1;
        nxt2 = (nxt2 == 2) ? 0 : nxt2 + 1;
    }

    // epilogue
    const int gr = lane >> 2;
    const int tg = lane & 3;
#pragma unroll
    for (int i = 0; i < 2; i++) {
        const int r0 = row0 + m0 + i * 16 + gr;
#pragma unroll
        for (int j = 0; j < 4; j++) {
            const int c = col0 + n0 + j * 8 + tg * 2;
            *(float2*)&C[(size_t)r0 * N + c]       = make_float2(d[i][j][0], d[i][j][1]);
            *(float2*)&C[(size_t)(r0 + 8) * N + c] = make_float2(d[i][j][2], d[i][j][3]);
        }
    }
}

// ---------------------------------------------------------------------------
// fp32 -> (hi, lo) bf16 split, vectorized
// ---------------------------------------------------------------------------
__global__ __launch_bounds__(256)
void split_kernel(const float* __restrict__ in, __nv_bfloat16* __restrict__ hi,
                  __nv_bfloat16* __restrict__ lo, int n4) {
    const int i = blockIdx.x * 256 + threadIdx.x;
    if (i >= n4) return;
    const float4 v = ((const float4*)in)[i];
    float f[4] = {v.x, v.y, v.z, v.w};
    __nv_bfloat16 h[4], l[4];
#pragma unroll
    for (int j = 0; j < 4; j++) {
        h[j] = __float2bfloat16(f[j]);
        l[j] = __float2bfloat16(f[j] - __bfloat162float(h[j]));
    }
    ((__nv_bfloat162*)hi)[2 * i]     = __nv_bfloat162(h[0], h[1]);
    ((__nv_bfloat162*)hi)[2 * i + 1] = __nv_bfloat162(h[2], h[3]);
    ((__nv_bfloat162*)lo)[2 * i]     = __nv_bfloat162(l[0], l[1]);
    ((__nv_bfloat162*)lo)[2 * i + 1] = __nv_bfloat162(l[2], l[3]);
}

// ---------------------------------------------------------------------------
// W[K,N] f32 -> W^T hi/lo bf16 [N,K]
// ---------------------------------------------------------------------------
__global__ __launch_bounds__(256)
void transpose_split(const float* __restrict__ in, __nv_bfloat16* __restrict__ hiT,
                     __nv_bfloat16* __restrict__ loT, int K, int N) {
    __shared__ float t[32][33];
    const int tx = threadIdx.x, ty = threadIdx.y;
    const int n0 = blockIdx.x * 32, k0 = blockIdx.y * 32;
#pragma unroll
    for (int i = 0; i < 4; i++)
        t[ty + 8 * i][tx] = in[(size_t)(k0 + ty + 8 * i) * N + n0 + tx];
    __syncthreads();
#pragma unroll
    for (int i = 0; i < 4; i++) {
        const float v = t[tx][ty + 8 * i];
        const __nv_bfloat16 h = __float2bfloat16(v);
        const __nv_bfloat16 l = __float2bfloat16(v - __bfloat162float(h));
        const size_t o = (size_t)(n0 + ty + 8 * i) * K + k0 + tx;
        hiT[o] = h;
        loT[o] = l;
    }
}

// ---------------------------------------------------------------------------
// Gaussian banded smoothing (WIN=16, 33 taps), row-normalized, f32x2 packed;
// emits bf16 hi/lo split directly.
// ---------------------------------------------------------------------------
__global__ __launch_bounds__(256)
void smooth_kernel(const float* __restrict__ y, __nv_bfloat16* __restrict__ shi,
                   __nv_bfloat16* __restrict__ slo, const float* __restrict__ sigma) {
    __shared__ float yt[TN + 2 * WIN][64];   // 96 x 64
    __shared__ float ew[2 * WIN + 1];        // 33 taps
    __shared__ float invZ[TN];

    const int n0 = blockIdx.x * TN;
    const int half = blockIdx.y;
    const int bh = blockIdx.z;
    const int b = bh >> 3;
    const int h = bh & 7;
    const int tid = threadIdx.x;

    const float* ybase = y + (size_t)b * NSEQ * INNER + h * DHEAD + half * 64;
    for (int i = tid; i < (TN + 2 * WIN) * 16; i += 256) {
        const int r = i >> 4;
        const int c = (i & 15) << 2;
        const int m = n0 - WIN + r;
        float4 v = make_float4(0.f, 0.f, 0.f, 0.f);
        if (m >= 0 && m < NSEQ) v = *(const float4*)(ybase + (size_t)m * INNER + c);
        *(float4*)&yt[r][c] = v;
    }
    if (tid < 2 * WIN + 1) {
        const float sg = sigma[h];
        const float dd = (float)(tid - WIN);
        ew[tid] = __expf(-dd * dd / (2.f * sg * sg));
    }
    __syncthreads();
    if (tid < TN) {
        const int n = n0 + tid;
        float z = 0.f;
#pragma unroll
        for (int j = 0; j <= 2 * WIN; j++) {
            const int m = n - WIN + j;
            if (m >= 0 && m < NSEQ) z += ew[j];
        }
        invZ[tid] = 1.f / z;
    }
    __syncthreads();

    const int cp = tid & 31;
    const int tg = tid >> 5;
#pragma unroll
    for (int k = 0; k < 8; k++) {
        const int t = tg * 8 + k;
        ull acc = 0ULL;
#pragma unroll
        for (int j = 0; j <= 2 * WIN; j++) {
            const ull w = pack_dup(ew[j]);
            const ull v = *(const ull*)&yt[t + j][cp << 1];
            ffma2(acc, w, v);
        }
        float ax, ay;
        unpack2(acc, ax, ay);
        const float iz = invZ[t];
        const float r0 = ax * iz, r1 = ay * iz;
        const __nv_bfloat16 h0 = __float2bfloat16(r0);
        const __nv_bfloat16 h1 = __float2bfloat16(r1);
        const __nv_bfloat16 l0 = __float2bfloat16(r0 - __bfloat162float(h0));
        const __nv_bfloat16 l1 = __float2bfloat16(r1 - __bfloat162float(h1));
        const int n = n0 + t;
        const size_t eo = ((size_t)b * NSEQ + n) * INNER + h * DHEAD + half * 64 + (cp << 1);
        *(__nv_bfloat162*)(shi + eo) = __nv_bfloat162(h0, h1);
        *(__nv_bfloat162*)(slo + eo) = __nv_bfloat162(l0, l1);
    }
}

// ---------------------------------------------------------------------------
extern "C" void kernel_launch(void* const* d_in, const int* in_sizes, int n_in,
                              void* d_out, int out_size) {
    const float* x     = (const float*)d_in[0];
    const float* Wg    = (const float*)d_in[1];
    const float* Wout  = (const float*)d_in[2];
    const float* sigma = (const float*)d_in[3];
    float* out = (float*)d_out;

    float *y; __nv_bfloat16 *xhi, *xlo, *shi, *slo, *wgh, *wgl, *woh, *wol;
    cudaGetSymbolAddress((void**)&y,   g_y);
    cudaGetSymbolAddress((void**)&xhi, g_xhi);
    cudaGetSymbolAddress((void**)&xlo, g_xlo);
    cudaGetSymbolAddress((void**)&shi, g_shi);
    cudaGetSymbolAddress((void**)&slo, g_slo);
    cudaGetSymbolAddress((void**)&wgh, g_wgT_hi);
    cudaGetSymbolAddress((void**)&wgl, g_wgT_lo);
    cudaGetSymbolAddress((void**)&woh, g_woT_hi);
    cudaGetSymbolAddress((void**)&wol, g_woT_lo);

    cudaFuncSetAttribute(gemm_mma, cudaFuncAttributeMaxDynamicSharedMemorySize, SMEM_GEMM);

    split_kernel<<<(MROWS * DIM / 4 + 255) / 256, 256>>>(x, xhi, xlo, MROWS * DIM / 4);
    transpose_split<<<dim3(INNER / 32, DIM / 32), dim3(32, 8)>>>(Wg, wgh, wgl, DIM, INNER);
    transpose_split<<<dim3(DIM / 32, INNER / 32), dim3(32, 8)>>>(Wout, woh, wol, INNER, DIM);

    gemm_mma<<<dim3(INNER / CTN, MROWS / CTM), 256, SMEM_GEMM>>>(
        xhi, xlo, wgh, wgl, y, MROWS, INNER, DIM);

    smooth_kernel<<<dim3(NSEQ / TN, 2, BATCH * NHEAD), 256>>>(y, shi, slo, sigma);

    gemm_mma<<<dim3(DIM / CTN, MROWS / CTM), 256, SMEM_GEMM>>>(
        shi, slo, woh, wol, out, MROWS, DIM, INNER);
}

// round 7
// speedup vs baseline: 1.3719x; 1.3719x over previous
#include <cuda_runtime.h>
#include <cuda_bf16.h>
#include <cstdint>
#include <cstddef>

// Problem constants
#define BATCH 4
#define NSEQ 2048
#define DIM 512
#define NHEAD 8
#define DHEAD 128
#define INNER 1024
#define MROWS (BATCH*NSEQ)  // 8192

#define WIN 16
#define TN 64

// ---------------- scratch (allocation-free rule) ----------------
// Packed tf32 operands: A atoms are 16x8 (128 f32 in m16n8k8 fragment order),
// B atoms are 8x8 (64 f32 in fragment order). Atom (i, kb) at ((i*kbT)+kb)*atom.
__device__ __align__(16) float g_y[MROWS * INNER];      // gemm1 out, f32 row-major
__device__ __align__(16) float g_xpk[MROWS * DIM];      // packed x   (A of GEMM1)
__device__ __align__(16) float g_spk[MROWS * INNER];    // packed s   (A of GEMM2)
__device__ __align__(16) float g_wgpk[INNER * DIM];     // packed Wg^T  (B of GEMM1)
__device__ __align__(16) float g_wopk[DIM * INNER];     // packed Wout^T (B of GEMM2)

// ---------------- helpers ----------------
typedef unsigned long long ull;
__device__ __forceinline__ ull pack_dup(float a) {
    ull r; asm("mov.b64 %0, {%1, %1};" : "=l"(r) : "f"(a)); return r;
}
__device__ __forceinline__ void ffma2(ull& d, ull a, ull b) {
    asm("fma.rn.f32x2 %0, %1, %2, %0;" : "+l"(d) : "l"(a), "l"(b));
}
__device__ __forceinline__ void unpack2(ull v, float& lo, float& hi) {
    asm("mov.b64 {%0, %1}, %2;" : "=f"(lo), "=f"(hi) : "l"(v));
}
__device__ __forceinline__ uint32_t smem_to_u32(const void* p) {
    uint32_t a;
    asm("{ .reg .u64 t; cvta.to.shared.u64 t, %1; cvt.u32.u64 %0, t; }" : "=r"(a) : "l"(p));
    return a;
}
__device__ __forceinline__ void cp16(uint32_t dst, const void* src) {
    asm volatile("cp.async.cg.shared.global [%0], [%1], 16;" :: "r"(dst), "l"(src) : "memory");
}
#define CP_COMMIT() asm volatile("cp.async.commit_group;" ::: "memory")
#define CP_WAIT1()  asm volatile("cp.async.wait_group 1;" ::: "memory")

__device__ __forceinline__ uint32_t f2tf(float f) {
    uint32_t r; asm("cvt.rna.tf32.f32 %0, %1;" : "=r"(r) : "f"(f)); return r;
}
__device__ __forceinline__ void lds128(uint32_t addr, uint32_t* r) {
    asm volatile("ld.shared.v4.b32 {%0,%1,%2,%3}, [%4];"
                 : "=r"(r[0]), "=r"(r[1]), "=r"(r[2]), "=r"(r[3]) : "r"(addr));
}
__device__ __forceinline__ void lds64(uint32_t addr, uint32_t* r) {
    asm volatile("ld.shared.v2.b32 {%0,%1}, [%2];"
                 : "=r"(r[0]), "=r"(r[1]) : "r"(addr));
}
__device__ __forceinline__ void mma_tf32(float* d, const uint32_t* a, const uint32_t* b) {
    asm volatile("mma.sync.aligned.m16n8k8.row.col.f32.tf32.tf32.f32 "
                 "{%0,%1,%2,%3}, {%4,%5,%6,%7}, {%8,%9}, {%0,%1,%2,%3};"
                 : "+f"(d[0]), "+f"(d[1]), "+f"(d[2]), "+f"(d[3])
                 : "r"(a[0]), "r"(a[1]), "r"(a[2]), "r"(a[3]), "r"(b[0]), "r"(b[1]));
}

// ---------------------------------------------------------------------------
// tf32 GEMM: C[M,N](f32) = A[M,K] @ B^T,  A/B pre-packed in fragment order.
// CTA tile 128x64, K-chunk 32, 8 warps, warp tile 32x32 (2m x 4n x 4k atoms).
// 3-stage cp.async pipeline; fragment loads are one LDS.128 / LDS.64 each.
// ---------------------------------------------------------------------------
#define CTM 128
#define CTN 64
#define TK  32
#define STG_A_BYTES 16384      // 32 A atoms x 512B  (8 mb x 4 kb)
#define STG_B_BYTES 8192       // 32 B atoms x 256B  (8 nb x 4 kb)
#define STAGE_BYTES (STG_A_BYTES + STG_B_BYTES)  // 24576
#define NSTAGE 3
#define SMEM_GEMM (NSTAGE * STAGE_BYTES)          // 73728

__global__ __launch_bounds__(256, 2)
void gemm_tf32(const float* __restrict__ Apk, const float* __restrict__ Bpk,
               float* __restrict__ C, int M, int N, int K) {
    extern __shared__ char smem[];
    const uint32_t sb = smem_to_u32(smem);
    const int tid = threadIdx.x;
    const int wid = tid >> 5;
    const int lane = tid & 31;
    const int row0 = blockIdx.y << 7;
    const int col0 = blockIdx.x << 6;
    const int kbT = K >> 3;             // k-blocks total
    const int mb0 = row0 >> 4;
    const int nb0 = col0 >> 3;

    const int wm = wid & 3;             // m-warp: 2 m-blocks each
    const int wn = wid >> 2;            // n-warp: 4 n-blocks each
    const int mbW = wm << 1;
    const int nbW = wn << 2;

    auto load_stage = [&](int buf, int kt) {
        const uint32_t st = sb + buf * STAGE_BYTES;
        const int kb0 = kt << 2;
        // A: 1024 x 16B chunks
#pragma unroll
        for (int r = 0; r < 4; r++) {
            const int i = tid + (r << 8);
            const int atomL = i >> 5;               // 0..31
            const int inner = (i & 31) << 4;        // bytes
            const int mbL = atomL >> 2, kbL = atomL & 3;
            const size_t g = ((size_t)(mb0 + mbL) * kbT + kb0 + kbL) * 512 + inner;
            cp16(st + (atomL << 9) + inner, (const char*)Apk + g);
        }
        // B: 512 x 16B chunks
#pragma unroll
        for (int r = 0; r < 2; r++) {
            const int i = tid + (r << 8);
            const int atomL = i >> 4;
            const int inner = (i & 15) << 4;
            const int nbL = atomL >> 2, kbL = atomL & 3;
            const size_t g = ((size_t)(nb0 + nbL) * kbT + kb0 + kbL) * 256 + inner;
            cp16(st + STG_A_BYTES + (atomL << 8) + inner, (const char*)Bpk + g);
        }
    };

    float d[2][4][4];
#pragma unroll
    for (int i = 0; i < 2; i++)
#pragma unroll
        for (int j = 0; j < 4; j++)
#pragma unroll
            for (int q = 0; q < 4; q++) d[i][j][q] = 0.f;

    const int KT = K / TK;
    load_stage(0, 0); CP_COMMIT();
    load_stage(1, 1); CP_COMMIT();

    const uint32_t la16 = (uint32_t)lane << 4;
    const uint32_t la8  = (uint32_t)lane << 3;

    int cur = 0, nxt2 = 2;
    for (int kt = 0; kt < KT; kt++) {
        CP_WAIT1();
        __syncthreads();
        if (kt + 2 < KT) load_stage(nxt2, kt + 2);
        CP_COMMIT();

        const uint32_t st = sb + cur * STAGE_BYTES;
#pragma unroll
        for (int ki = 0; ki < 4; ki++) {
            uint32_t a[2][4], b[4][2];
#pragma unroll
            for (int mi = 0; mi < 2; mi++)
                lds128(st + (uint32_t)((((mbW + mi) << 2) + ki) << 9) + la16, a[mi]);
#pragma unroll
            for (int ni = 0; ni < 4; ni++)
                lds64(st + STG_A_BYTES + (uint32_t)((((nbW + ni) << 2) + ki) << 8) + la8, b[ni]);
#pragma unroll
            for (int mi = 0; mi < 2; mi++)
#pragma unroll
                for (int ni = 0; ni < 4; ni++)
                    mma_tf32(d[mi][ni], a[mi], b[ni]);
        }
        cur  = (cur == 2)  ? 0 : cur + 1;
        nxt2 = (nxt2 == 2) ? 0 : nxt2 + 1;
    }

    // epilogue: atom (mi, ni) -> rows (g, g+8), cols (tg*2, +1)
    const int gr = lane >> 2;
    const int tg = lane & 3;
#pragma unroll
    for (int mi = 0; mi < 2; mi++) {
        const int r0 = row0 + (wm << 5) + (mi << 4) + gr;
#pragma unroll
        for (int ni = 0; ni < 4; ni++) {
            const int c = col0 + (wn << 5) + (ni << 3) + (tg << 1);
            *(float2*)&C[(size_t)r0 * N + c]       = make_float2(d[mi][ni][0], d[mi][ni][1]);
            *(float2*)&C[(size_t)(r0 + 8) * N + c] = make_float2(d[mi][ni][2], d[mi][ni][3]);
        }
    }
}

// ---------------------------------------------------------------------------
// pack_a: row-major [M,K] f32 -> packed tf32 A atoms (16x8, fragment order)
// thread t -> atom (t>>5), lane (t&31): writes 4 contiguous values.
// ---------------------------------------------------------------------------
__global__ __launch_bounds__(256)
void pack_a(const float* __restrict__ src, float* __restrict__ dst, int M, int K) {
    const int t = blockIdx.x * 256 + threadIdx.x;
    const int kbT = K >> 3;
    const int atom = t >> 5;
    if (atom >= (M >> 4) * kbT) return;
    const int lane = t & 31;
    const int mb = atom / kbT, kb = atom % kbT;
    const int g = lane >> 2, tt = lane & 3;
    const int r = mb * 16 + g, c = kb * 8 + tt;
    uint4 o;
    o.x = f2tf(src[(size_t)r * K + c]);            // (g,   t)
    o.y = f2tf(src[(size_t)(r + 8) * K + c]);      // (g+8, t)
    o.z = f2tf(src[(size_t)r * K + c + 4]);        // (g,   t+4)
    o.w = f2tf(src[(size_t)(r + 8) * K + c + 4]);  // (g+8, t+4)
    *(uint4*)(dst + (size_t)atom * 128 + lane * 4) = o;
}

// ---------------------------------------------------------------------------
// pack_w: W[K,N] f32 row-major -> packed tf32 B atoms of W^T (8x8 fragment order)
// b0 = WT[nb*8+g, kb*8+tt] = W[kb*8+tt, nb*8+g]; b1 at +4 k.
// ---------------------------------------------------------------------------
__global__ __launch_bounds__(256)
void pack_w(const float* __restrict__ W, float* __restrict__ dst, int K, int N) {
    const int t = blockIdx.x * 256 + threadIdx.x;
    const int kbT = K >> 3;
    const int atom = t >> 5;
    if (atom >= (N >> 3) * kbT) return;
    const int lane = t & 31;
    const int nb = atom / kbT, kb = atom % kbT;
    const int g = lane >> 2, tt = lane & 3;
    uint2 o;
    o.x = f2tf(W[(size_t)(kb * 8 + tt) * N + nb * 8 + g]);
    o.y = f2tf(W[(size_t)(kb * 8 + tt + 4) * N + nb * 8 + g]);
    *(uint2*)(dst + (size_t)atom * 64 + lane * 2) = o;
}

// ---------------------------------------------------------------------------
// Gaussian banded smoothing (WIN=16), row-normalized, f32x2 packed math;
// writes s directly in packed tf32 A-fragment layout for GEMM2.
// ---------------------------------------------------------------------------
__global__ __launch_bounds__(256)
void smooth_kernel(const float* __restrict__ y, float* __restrict__ spk,
                   const float* __restrict__ sigma) {
    __shared__ float yt[TN + 2 * WIN][64];
    __shared__ float ew[2 * WIN + 1];
    __shared__ float invZ[TN];

    const int n0 = blockIdx.x * TN;
    const int half = blockIdx.y;
    const int bh = blockIdx.z;
    const int b = bh >> 3;
    const int h = bh & 7;
    const int tid = threadIdx.x;

    const float* ybase = y + (size_t)b * NSEQ * INNER + h * DHEAD + half * 64;
    for (int i = tid; i < (TN + 2 * WIN) * 16; i += 256) {
        const int r = i >> 4;
        const int c = (i & 15) << 2;
        const int m = n0 - WIN + r;
        float4 v = make_float4(0.f, 0.f, 0.f, 0.f);
        if (m >= 0 && m < NSEQ) v = *(const float4*)(ybase + (size_t)m * INNER + c);
        *(float4*)&yt[r][c] = v;
    }
    if (tid < 2 * WIN + 1) {
        const float sg = sigma[h];
        const float dd = (float)(tid - WIN);
        ew[tid] = __expf(-dd * dd / (2.f * sg * sg));
    }
    __syncthreads();
    if (tid < TN) {
        const int n = n0 + tid;
        float z = 0.f;
#pragma unroll
        for (int j = 0; j <= 2 * WIN; j++) {
            const int m = n - WIN + j;
            if (m >= 0 && m < NSEQ) z += ew[j];
        }
        invZ[tid] = 1.f / z;
    }
    __syncthreads();

    const int cp = tid & 31;     // channel pair index 0..31
    const int tg = tid >> 5;     // 0..7
    const int c0 = h * DHEAD + half * 64 + (cp << 1);   // global channel (even)
    const int kb = c0 >> 3;
    const int cc = c0 & 7;
#pragma unroll
    for (int k = 0; k < 8; k++) {
        const int t = tg * 8 + k;
        ull acc = 0ULL;
#pragma unroll
        for (int j = 0; j <= 2 * WIN; j++) {
            const ull w = pack_dup(ew[j]);
            const ull v = *(const ull*)&yt[t + j][cp << 1];
            ffma2(acc, w, v);
        }
        float ax, ay;
        unpack2(acc, ax, ay);
        const float iz = invZ[t];
        const uint32_t v0 = f2tf(ax * iz);
        const uint32_t v1 = f2tf(ay * iz);
        // packed A layout for GEMM2: m = b*NSEQ + n
        const int m = b * NSEQ + n0 + t;
        const int mb = m >> 4;
        const int r = m & 15;
        const int lane0 = ((r & 7) << 2) + (cc & 3);
        const int q = (((cc >> 2) & 1) << 1) + ((r >> 3) & 1);
        const size_t base = ((size_t)mb * (INNER / 8) + kb) * 128 + lane0 * 4 + q;
        ((uint32_t*)spk)[base]     = v0;   // channel c0   (lane0)
        ((uint32_t*)spk)[base + 4] = v1;   // channel c0+1 (lane0+1)
    }
}

// ---------------------------------------------------------------------------
extern "C" void kernel_launch(void* const* d_in, const int* in_sizes, int n_in,
                              void* d_out, int out_size) {
    const float* x     = (const float*)d_in[0];
    const float* Wg    = (const float*)d_in[1];
    const float* Wout  = (const float*)d_in[2];
    const float* sigma = (const float*)d_in[3];
    float* out = (float*)d_out;

    float *y, *xpk, *spk, *wgpk, *wopk;
    cudaGetSymbolAddress((void**)&y,    g_y);
    cudaGetSymbolAddress((void**)&xpk,  g_xpk);
    cudaGetSymbolAddress((void**)&spk,  g_spk);
    cudaGetSymbolAddress((void**)&wgpk, g_wgpk);
    cudaGetSymbolAddress((void**)&wopk, g_wopk);

    cudaFuncSetAttribute(gemm_tf32, cudaFuncAttributeMaxDynamicSharedMemorySize, SMEM_GEMM);

    // prep: pack x, Wg^T, Wout^T into tf32 fragment layouts
    {
        const int tA = (MROWS / 16) * (DIM / 8) * 32;         // 1,048,576
        pack_a<<<tA / 256, 256>>>(x, xpk, MROWS, DIM);
        const int tW1 = (INNER / 8) * (DIM / 8) * 32;         // 262,144
        pack_w<<<tW1 / 256, 256>>>(Wg, wgpk, DIM, INNER);
        const int tW2 = (DIM / 8) * (INNER / 8) * 32;
        pack_w<<<tW2 / 256, 256>>>(Wout, wopk, INNER, DIM);
    }

    // GEMM1: y[8192,1024] = x @ Wg
    gemm_tf32<<<dim3(INNER / CTN, MROWS / CTM), 256, SMEM_GEMM>>>(
        xpk, wgpk, y, MROWS, INNER, DIM);

    // banded Gaussian attention -> s (packed tf32)
    smooth_kernel<<<dim3(NSEQ / TN, 2, BATCH * NHEAD), 256>>>(y, spk, sigma);

    // GEMM2: out[8192,512] = s @ Wout
    gemm_tf32<<<dim3(DIM / CTN, MROWS / CTM), 256, SMEM_GEMM>>>(
        spk, wopk, out, MROWS, DIM, INNER);
}